// round 10
// baseline (speedup 1.0000x reference)
#include <cuda_runtime.h>

namespace qc {

constexpr int NQ = 14;
constexpr int NL = 4;
constexpr int NS = 1 << NQ;       // 16384 amplitudes
constexpr int NT = 1024;          // 32 warps; lane-pair shares a 32-amp window
constexpr int NC = NQ - 1;
constexpr int NWARP = NT / 32;
constexpr int NGL = NL - 1;       // gate layers stored (layers 1..3)

// shared memory layout (float offsets). State float2[NS].
constexpr int OFF_U   = 2 * NS;                    // 42 gates * 8 floats
constexpr int OFF_V   = OFF_U + NGL * NQ * 8;      // 14 qubits * 2 cplx
constexpr int OFF_RED = OFF_V + NQ * 4;
constexpr int SMEM_FLOATS = OFF_RED + NWARP * NQ;
constexpr int SMEM_BYTES  = SMEM_FLOATS * 4;

__device__ __forceinline__ int swz(int i) { return i ^ ((i >> 5) & 31); }

__device__ __forceinline__ float2 cmul(float2 a, float2 b) {
  return make_float2(a.x * b.x - a.y * b.y, a.x * b.y + a.y * b.x);
}

// prefix-xor relabel for the in-window CNOT chain (compile-time)
__host__ __device__ constexpr int pxm(int o) {
  return (o ^ (o << 1) ^ (o << 2) ^ (o << 3)) & 15;
}

// ---- window addressing: 16 amps in-thread (bits S..S+3), bit S+4 = lane parity ----
template<int S>
__device__ __forceinline__ int wbase(int g, int p) {
  return (((g >> S) << (S + 5)) | (g & ((1 << S) - 1))) | (p << (S + 4));
}

template<int S>
__device__ __forceinline__ void load16(const float2* __restrict__ st, int g, int p,
                                       float* vr, float* vi) {
  const int base = wbase<S>(g, p);
#pragma unroll
  for (int o = 0; o < 16; ++o) {
    const float2 v = st[swz(base | (o << S))];
    vr[o] = v.x; vi[o] = v.y;
  }
}

// store; if PX, relabel o -> pxm(o) (folds in-window CNOT chain); cbmask folds
// a control-outside CNOT: XOR applied to the LABEL (not the base — OR would
// clobber it; that was the r8/r9 corruption bug).
template<int S, bool PX>
__device__ __forceinline__ void store16(float2* __restrict__ st, int g, int p,
                                        const float* vr, const float* vi, int cbmask) {
  const int base = wbase<S>(g, p);
#pragma unroll
  for (int o = 0; o < 16; ++o) {
    const int m = (PX ? pxm(o) : o) ^ cbmask;
    st[swz(base | (m << S))] = make_float2(vr[o], vi[o]);
  }
}

// in-thread 1q gate butterfly on local bit J
template<int J>
__device__ __forceinline__ void gateBit(float* vr, float* vi, const float* __restrict__ u) {
  const float u0 = u[0], u1 = u[1], u2 = u[2], u3 = u[3];
  const float u4 = u[4], u5 = u[5], u6 = u[6], u7 = u[7];
#pragma unroll
  for (int o = 0; o < 16; ++o) {
    if (o & (1 << J)) continue;
    const int o1 = o | (1 << J);
    const float ar = vr[o], ai = vi[o], br = vr[o1], bi = vi[o1];
    vr[o]  = u0*ar - u1*ai + u2*br - u3*bi;
    vi[o]  = u0*ai + u1*ar + u2*bi + u3*br;
    vr[o1] = u4*ar - u5*ai + u6*br - u7*bi;
    vi[o1] = u4*ai + u5*ar + u6*bi + u7*br;
  }
}

// cross-lane 1q gate on local bit 4 (= lane parity). Uses SU(2) structure
// (u4=-u2, u5=u3, u6=u0, u7=-u1): out = C*own + D*partner, row picked by p.
__device__ __forceinline__ void sGate(float* vr, float* vi, const float* __restrict__ u, int p) {
  const float Cre = u[0];
  const float Cim = p ? -u[1] : u[1];
  const float Dre = p ? -u[2] : u[2];
  const float Dim = u[3];
#pragma unroll
  for (int o = 0; o < 16; ++o) {
    const float pr = __shfl_xor_sync(0xffffffffu, vr[o], 16);
    const float pi = __shfl_xor_sync(0xffffffffu, vi[o], 16);
    const float ar = vr[o], ai = vi[o];
    vr[o] = Cre*ar - Cim*ai + Dre*pr - Dim*pi;
    vi[o] = Cre*ai + Cim*ar + Dre*pi + Dim*pr;
  }
}

// CNOT exchange across bit 4: swap with partner where parity(o) == PC
template<int PC>
__device__ __forceinline__ void exch(float* vr, float* vi) {
#pragma unroll
  for (int o = 0; o < 16; ++o) {
    if ((__popc(o) & 1) == PC) {
      vr[o] = __shfl_xor_sync(0xffffffffu, vr[o], 16);
      vi[o] = __shfl_xor_sync(0xffffffffu, vi[o], 16);
    }
  }
}

__global__ void __launch_bounds__(NT, 1)
qc_kernel(const float* __restrict__ x, const float* __restrict__ prx,
          const float* __restrict__ pry, const float* __restrict__ prz,
          const float* __restrict__ pent, float* __restrict__ out) {
  extern __shared__ float sm[];
  float2* st = reinterpret_cast<float2*>(sm);
  float2* vv = reinterpret_cast<float2*>(sm + OFF_V);
  const int tid  = threadIdx.x;
  const int lane = tid & 31;
  const int g    = (tid >> 5) * 16 + (lane & 15);   // window id 0..511
  const int p    = (lane >> 4) & 1;                 // window bit 4
  const int b    = blockIdx.x;

  // ---- prologue: gates for layers 1..3 (U' = Rz*Ry*Rx * RZ_ent[l-1]) ----
  if (tid < NGL * NQ) {
    const int q = tid % NQ;
    const int idx = tid + NQ;
    float cx, sx, cy, sy, cz, sz;
    sincosf(0.5f * prx[idx], &sx, &cx);
    sincosf(0.5f * pry[idx], &sy, &cy);
    sincosf(0.5f * prz[idx], &sz, &cz);
    const float r00x =  cy*cx, r00y =  sy*sx;
    const float r01x = -sy*cx, r01y = -cy*sx;
    const float r10x =  sy*cx, r10y = -cy*sx;
    const float r11x =  cy*cx, r11y = -sy*sx;
    float u0 = r00x*cz + r00y*sz, u1 = r00y*cz - r00x*sz;
    float u2 = r01x*cz + r01y*sz, u3 = r01y*cz - r01x*sz;
    float u4 = r10x*cz - r10y*sz, u5 = r10x*sz + r10y*cz;
    float u6 = r11x*cz - r11y*sz, u7 = r11x*sz + r11y*cz;
    if (q >= 1) {
      float c, s; sincosf(0.5f * pent[(tid / NQ) * NC + (q - 1)], &s, &c);
      float a;
      a = u0*c + u1*s;  u1 = u1*c - u0*s;  u0 = a;   // col 0 *= e^{-i t/2}
      a = u4*c + u5*s;  u5 = u5*c - u4*s;  u4 = a;
      a = u2*c - u3*s;  u3 = u3*c + u2*s;  u2 = a;   // col 1 *= e^{+i t/2}
      a = u6*c - u7*s;  u7 = u7*c + u6*s;  u6 = a;
    }
    float* u = sm + OFF_U + tid * 8;
    u[0] = u0; u[1] = u1; u[2] = u2; u[3] = u3;
    u[4] = u4; u[5] = u5; u[6] = u6; u[7] = u7;
  }
  // ---- layer-0 gates folded into product vectors: v_j = U_0(j)*(c_j,s_j)^T ----
  if (tid >= 64 && tid < 64 + NQ) {
    const int j = tid - 64;
    float cx, sx, cy, sy, cz, sz;
    sincosf(0.5f * prx[j], &sx, &cx);
    sincosf(0.5f * pry[j], &sy, &cy);
    sincosf(0.5f * prz[j], &sz, &cz);
    const float r00x =  cy*cx, r00y =  sy*sx;
    const float r01x = -sy*cx, r01y = -cy*sx;
    const float r10x =  sy*cx, r10y = -cy*sx;
    const float r11x =  cy*cx, r11y = -sy*sx;
    const float u0 = r00x*cz + r00y*sz, u1 = r00y*cz - r00x*sz;
    const float u2 = r01x*cz + r01y*sz, u3 = r01y*cz - r01x*sz;
    const float u4 = r10x*cz - r10y*sz, u5 = r10x*sz + r10y*cz;
    const float u6 = r11x*cz - r11y*sz, u7 = r11x*sz + r11y*cz;
    const float th = 0.5f * 3.14159265358979323846f * tanhf(x[b * NQ + j]);
    float c, s; sincosf(th, &s, &c);
    vv[j * 2 + 0] = make_float2(u0 * c + u2 * s, u1 * c + u3 * s);
    vv[j * 2 + 1] = make_float2(u4 * c + u6 * s, u5 * c + u7 * s);
  }
  __syncthreads();

  const float* ul1 = sm + OFF_U;
  const float* ul2 = sm + OFF_U + 14 * 8;
  const float* ul3 = sm + OFF_U + 28 * 8;
  const int cb = (g >> 4) & 1;          // qubit-4 value for S=5 windows (warp-uniform)
  float vr[16], vi[16];

  // ================= P1: synth + G1(0-4) + C1(0-3)  [S=0] =================
  {
    // amp(y) = prod v_j[x_j], x_j = y_j^y_{j-1}; y bits: 0-3=o, 4=p, 5-13=g
    float2 Pg = vv[5 * 2 + ((g ^ p) & 1)];
#pragma unroll
    for (int j = 6; j < NQ; ++j)
      Pg = cmul(Pg, vv[j * 2 + (((g >> (j - 5)) ^ (g >> (j - 6))) & 1)]);
    float2 t4[2];                      // o3 -> v4[p^o3]*Pg
    t4[0] = cmul(vv[4 * 2 + p], Pg);
    t4[1] = cmul(vv[4 * 2 + (p ^ 1)], Pg);
    float2 r34[4];                     // [o2 + 2*o3]
#pragma unroll
    for (int o2 = 0; o2 < 2; ++o2)
#pragma unroll
      for (int o3 = 0; o3 < 2; ++o3)
        r34[o2 + 2 * o3] = cmul(vv[3 * 2 + (o3 ^ o2)], t4[o3]);
    float2 qv[8];                      // [o1 + 2*o2 + 4*o3]
#pragma unroll
    for (int o1 = 0; o1 < 2; ++o1)
#pragma unroll
      for (int o2 = 0; o2 < 2; ++o2)
#pragma unroll
        for (int o3 = 0; o3 < 2; ++o3)
          qv[o1 + 2 * o2 + 4 * o3] = cmul(vv[2 * 2 + (o2 ^ o1)], r34[o2 + 2 * o3]);
    float2 e01[4];                     // [o0 + 2*o1]
#pragma unroll
    for (int o0 = 0; o0 < 2; ++o0)
#pragma unroll
      for (int o1 = 0; o1 < 2; ++o1)
        e01[o0 + 2 * o1] = cmul(vv[0 * 2 + o0], vv[1 * 2 + (o1 ^ o0)]);
#pragma unroll
    for (int o = 0; o < 16; ++o) {
      const float2 a = cmul(e01[o & 3], qv[(o >> 1) & 7]);
      vr[o] = a.x; vi[o] = a.y;
    }
    gateBit<0>(vr, vi, ul1 + 0 * 8);
    gateBit<1>(vr, vi, ul1 + 1 * 8);
    gateBit<2>(vr, vi, ul1 + 2 * 8);
    gateBit<3>(vr, vi, ul1 + 3 * 8);
    sGate(vr, vi, ul1 + 4 * 8, p);
    exch<1>(vr, vi);                                // c3: control = parity(o)
    store16<0, true>(st, g, p, vr, vi, 0);          // c0-c2 folded via PX relabel
  }
  __syncthreads();

  // ================= P2: G1(5-9) + C1(4-8)  [S=5] =================
  {
    load16<5>(st, g, p, vr, vi);
    gateBit<0>(vr, vi, ul1 + 5 * 8);
    gateBit<1>(vr, vi, ul1 + 6 * 8);
    gateBit<2>(vr, vi, ul1 + 7 * 8);
    gateBit<3>(vr, vi, ul1 + 8 * 8);
    sGate(vr, vi, ul1 + 9 * 8, p);
    if (cb) exch<0>(vr, vi); else exch<1>(vr, vi);  // c8: control = parity(o)^cb
    store16<5, true>(st, g, p, vr, vi, cb ? 15 : 0); // c4 (ctrl outside) + c5-c7 folded
  }
  __syncthreads();

  // ================= P3: G1(10-13) + C1(9-12) + G2(9-13)  [S=9] =================
  {
    load16<9>(st, g, p, vr, vi);
    gateBit<1>(vr, vi, ul1 + 10 * 8);
    gateBit<2>(vr, vi, ul1 + 11 * 8);
    gateBit<3>(vr, vi, ul1 + 12 * 8);
    sGate(vr, vi, ul1 + 13 * 8, p);
    exch<1>(vr, vi);                                 // c12 BEFORE relabel: ctrl=parity(o)
    float wr[16], wi[16];                            // relabel c9-c11
#pragma unroll
    for (int o = 0; o < 16; ++o) { wr[pxm(o)] = vr[o]; wi[pxm(o)] = vi[o]; }
    gateBit<0>(wr, wi, ul2 + 9 * 8);
    gateBit<1>(wr, wi, ul2 + 10 * 8);
    gateBit<2>(wr, wi, ul2 + 11 * 8);
    gateBit<3>(wr, wi, ul2 + 12 * 8);
    sGate(wr, wi, ul2 + 13 * 8, p);
    store16<9, false>(st, g, p, wr, wi, 0);
  }
  __syncthreads();

  // ================= P4: G2(0-4) + C2(0-3)  [S=0] =================
  {
    load16<0>(st, g, p, vr, vi);
    gateBit<0>(vr, vi, ul2 + 0 * 8);
    gateBit<1>(vr, vi, ul2 + 1 * 8);
    gateBit<2>(vr, vi, ul2 + 2 * 8);
    gateBit<3>(vr, vi, ul2 + 3 * 8);
    sGate(vr, vi, ul2 + 4 * 8, p);
    exch<1>(vr, vi);
    store16<0, true>(st, g, p, vr, vi, 0);
  }
  __syncthreads();

  // ================= P5: G2(5-8) + C2(4-8)  [S=5] =================
  {
    load16<5>(st, g, p, vr, vi);
    gateBit<0>(vr, vi, ul2 + 5 * 8);
    gateBit<1>(vr, vi, ul2 + 6 * 8);
    gateBit<2>(vr, vi, ul2 + 7 * 8);
    gateBit<3>(vr, vi, ul2 + 8 * 8);
    // G2(9) already applied in P3
    if (cb) exch<0>(vr, vi); else exch<1>(vr, vi);
    store16<5, true>(st, g, p, vr, vi, cb ? 15 : 0);
  }
  __syncthreads();

  // ================= P6: C2(9-12) + G3(9-13)  [S=9] =================
  {
    load16<9>(st, g, p, vr, vi);
    exch<1>(vr, vi);                                 // c12 BEFORE relabel: ctrl=parity(o)
    float wr[16], wi[16];
#pragma unroll
    for (int o = 0; o < 16; ++o) { wr[pxm(o)] = vr[o]; wi[pxm(o)] = vi[o]; }
    gateBit<0>(wr, wi, ul3 + 9 * 8);
    gateBit<1>(wr, wi, ul3 + 10 * 8);
    gateBit<2>(wr, wi, ul3 + 11 * 8);
    gateBit<3>(wr, wi, ul3 + 12 * 8);
    sGate(wr, wi, ul3 + 13 * 8, p);
    store16<9, false>(st, g, p, wr, wi, 0);
  }
  __syncthreads();

  // ================= P7: G3(0-4) + C3(0-3)  [S=0] =================
  {
    load16<0>(st, g, p, vr, vi);
    gateBit<0>(vr, vi, ul3 + 0 * 8);
    gateBit<1>(vr, vi, ul3 + 1 * 8);
    gateBit<2>(vr, vi, ul3 + 2 * 8);
    gateBit<3>(vr, vi, ul3 + 3 * 8);
    sGate(vr, vi, ul3 + 4 * 8, p);
    exch<1>(vr, vi);
    store16<0, true>(st, g, p, vr, vi, 0);
  }
  __syncthreads();

  // ================= P8: G3(5-8) + C3(4-8)  [S=5] =================
  {
    load16<5>(st, g, p, vr, vi);
    gateBit<0>(vr, vi, ul3 + 5 * 8);
    gateBit<1>(vr, vi, ul3 + 6 * 8);
    gateBit<2>(vr, vi, ul3 + 7 * 8);
    gateBit<3>(vr, vi, ul3 + 8 * 8);
    if (cb) exch<0>(vr, vi); else exch<1>(vr, vi);
    store16<5, true>(st, g, p, vr, vi, cb ? 15 : 0);
  }
  __syncthreads();

  // ================= P9: C3(9-12) + MEAS  [S=9] =================
  float acc[NQ];
  {
    load16<9>(st, g, p, vr, vi);
    float tot = 0.0f, s0 = 0.0f, s1 = 0.0f, s2 = 0.0f, s3 = 0.0f;
#pragma unroll
    for (int o = 0; o < 16; ++o) {
      const float pr = vr[o] * vr[o] + vi[o] * vi[o];
      const int m = pxm(o);              // labels after c9-c11 (no data movement)
      tot += pr;
      if (m & 1) s0 += pr;
      if (m & 2) s1 += pr;
      if (m & 4) s2 += pr;
      if (m & 8) s3 += pr;
    }
    acc[9]  = tot - 2.0f * s0;
    acc[10] = tot - 2.0f * s1;
    acc[11] = tot - 2.0f * s2;
    acc[12] = tot - 2.0f * s3;
    acc[13] = p ? (2.0f * s3 - tot) : (tot - 2.0f * s3);   // q13 = p ^ m3 (c12 folded)
#pragma unroll
    for (int q = 0; q < 9; ++q)
      acc[q] = ((g >> q) & 1) ? -tot : tot;
  }

  // ---- reduction ----
#pragma unroll
  for (int q = 0; q < NQ; ++q)
#pragma unroll
    for (int off = 16; off > 0; off >>= 1)
      acc[q] += __shfl_xor_sync(0xffffffffu, acc[q], off);
  const int warp = tid >> 5;
  __syncthreads();
  if ((tid & 31) == 0) {
#pragma unroll
    for (int q = 0; q < NQ; ++q) sm[OFF_RED + warp * NQ + q] = acc[q];
  }
  __syncthreads();
  if (tid < NQ) {
    float s = 0.0f;
#pragma unroll
    for (int w = 0; w < NWARP; ++w) s += sm[OFF_RED + w * NQ + tid];
    out[b * NQ + tid] = s;
  }
}

} // namespace qc

extern "C" void kernel_launch(void* const* d_in, const int* in_sizes, int n_in,
                              void* d_out, int out_size) {
  const float* x    = (const float*)d_in[0];
  const float* prx  = (const float*)d_in[1];
  const float* pry  = (const float*)d_in[2];
  const float* prz  = (const float*)d_in[3];
  const float* pent = (const float*)d_in[4];
  float* out = (float*)d_out;
  const int batch = in_sizes[0] / qc::NQ;   // 128
  cudaFuncSetAttribute(qc::qc_kernel, cudaFuncAttributeMaxDynamicSharedMemorySize,
                       qc::SMEM_BYTES);
  qc::qc_kernel<<<batch, qc::NT, qc::SMEM_BYTES>>>(x, prx, pry, prz, pent, out);
}

// round 11
// speedup vs baseline: 1.0063x; 1.0063x over previous
#include <cuda_runtime.h>

namespace qc {

constexpr int NQ = 14;
constexpr int NL = 4;
constexpr int NS = 1 << NQ;       // 16384 amplitudes
constexpr int NT = 1024;          // 32 warps; lane-pair shares a 32-amp window
constexpr int NC = NQ - 1;
constexpr int NWARP = NT / 32;
constexpr int NGL = NL - 1;       // gate layers stored (layers 1..3)

// shared memory layout (float offsets). State float2[NS].
constexpr int OFF_U   = 2 * NS;                    // 42 gates * 8 floats
constexpr int OFF_V   = OFF_U + NGL * NQ * 8;      // 14 qubits * 2 cplx
constexpr int OFF_RED = OFF_V + NQ * 4;
constexpr int SMEM_FLOATS = OFF_RED + NWARP * NQ;
constexpr int SMEM_BYTES  = SMEM_FLOATS * 4;

__device__ __forceinline__ int swz(int i) { return i ^ ((i >> 5) & 31); }

__device__ __forceinline__ float2 cmul(float2 a, float2 b) {
  return make_float2(a.x * b.x - a.y * b.y, a.x * b.y + a.y * b.x);
}

// prefix-xor relabel for the in-window CNOT chain (compile-time)
__host__ __device__ constexpr int pxm(int o) {
  return (o ^ (o << 1) ^ (o << 2) ^ (o << 3)) & 15;
}

// ---- window addressing: 16 amps in-thread (bits S..S+3), bit S+4 = lane parity ----
template<int S>
__device__ __forceinline__ int wbase(int g, int p) {
  return (((g >> S) << (S + 5)) | (g & ((1 << S) - 1))) | (p << (S + 4));
}

template<int S>
__device__ __forceinline__ void load16(const float2* __restrict__ st, int g, int p,
                                       float* vr, float* vi) {
  const int base = wbase<S>(g, p);
#pragma unroll
  for (int o = 0; o < 16; ++o) {
    const float2 v = st[swz(base | (o << S))];
    vr[o] = v.x; vi[o] = v.y;
  }
}

// load with a folded exch (swap where parity(o)==1): odd-parity elements load
// from the partner lane's slot (bit S+4 flipped). Pure address math, no shuffles.
template<int S>
__device__ __forceinline__ void loadSwap16(const float2* __restrict__ st, int g, int p,
                                           float* vr, float* vi) {
  const int baseA = wbase<S>(g, p);
  const int baseF = baseA ^ (1 << (S + 4));
#pragma unroll
  for (int o = 0; o < 16; ++o) {
    const int base = (__popc(o) & 1) ? baseF : baseA;
    const float2 v = st[swz(base | (o << S))];
    vr[o] = v.x; vi[o] = v.y;
  }
}

// store; if PX, relabel o -> pxm(o) (folds in-window CNOT chain); cbmask folds
// a control-outside CNOT: XOR applied to the LABEL.
template<int S, bool PX>
__device__ __forceinline__ void store16(float2* __restrict__ st, int g, int p,
                                        const float* vr, const float* vi, int cbmask) {
  const int base = wbase<S>(g, p);
#pragma unroll
  for (int o = 0; o < 16; ++o) {
    const int m = (PX ? pxm(o) : o) ^ cbmask;
    st[swz(base | (m << S))] = make_float2(vr[o], vi[o]);
  }
}

// store with relabel + cbmask + folded cond-exch: element o goes to the partner
// lane's slot where flip(o) = parity(o) ^ cb. cb is warp-uniform -> conflict-free.
template<int S>
__device__ __forceinline__ void storeSwap16(float2* __restrict__ st, int g, int p,
                                            const float* vr, const float* vi,
                                            int cbmask, int cb) {
  const int baseA = wbase<S>(g, p);
  const int baseF = baseA ^ (1 << (S + 4));
  const int baseEven = cb ? baseF : baseA;   // parity 0: flip = cb
  const int baseOdd  = cb ? baseA : baseF;   // parity 1: flip = cb^1
#pragma unroll
  for (int o = 0; o < 16; ++o) {
    const int m = pxm(o) ^ cbmask;
    const int base = (__popc(o) & 1) ? baseOdd : baseEven;
    st[swz(base | (m << S))] = make_float2(vr[o], vi[o]);
  }
}

// in-thread 1q gate butterfly on local bit J
template<int J>
__device__ __forceinline__ void gateBit(float* vr, float* vi, const float* __restrict__ u) {
  const float u0 = u[0], u1 = u[1], u2 = u[2], u3 = u[3];
  const float u4 = u[4], u5 = u[5], u6 = u[6], u7 = u[7];
#pragma unroll
  for (int o = 0; o < 16; ++o) {
    if (o & (1 << J)) continue;
    const int o1 = o | (1 << J);
    const float ar = vr[o], ai = vi[o], br = vr[o1], bi = vi[o1];
    vr[o]  = u0*ar - u1*ai + u2*br - u3*bi;
    vi[o]  = u0*ai + u1*ar + u2*bi + u3*br;
    vr[o1] = u4*ar - u5*ai + u6*br - u7*bi;
    vi[o1] = u4*ai + u5*ar + u6*bi + u7*br;
  }
}

// cross-lane 1q gate on local bit 4 (= lane parity), no exchange.
// SU(2) structure (u4=-u2, u5=u3, u6=u0, u7=-u1): out = C*own + D*partner.
__device__ __forceinline__ void sGate(float* vr, float* vi, const float* __restrict__ u, int p) {
  const float Cre = u[0];
  const float Cim = p ? -u[1] : u[1];
  const float Dre = p ? -u[2] : u[2];
  const float Dim = u[3];
#pragma unroll
  for (int o = 0; o < 16; ++o) {
    const float pr = __shfl_xor_sync(0xffffffffu, vr[o], 16);
    const float pi = __shfl_xor_sync(0xffffffffu, vi[o], 16);
    const float ar = vr[o], ai = vi[o];
    vr[o] = Cre*ar - Cim*ai + Dre*pr - Dim*pi;
    vi[o] = Cre*ai + Cim*ar + Dre*pi + Dim*pr;
  }
}

// MERGED cross-lane gate + CNOT-exchange. Swap condition c(o) = parity(o) ^ CBX.
//   c=0: out = C(p)*own + D(p)*partner
//   c=1: out = D(pbar)*own + C(pbar)*partner   (gate-then-swap, exact)
// With u1s = (p? -u1:u1), u2s = (p? -u2:u2):
//   C(p)=(u0,u1s) D(p)=(u2s,u3); D(pbar)=(-u2s,u3) C(pbar)=(u0,-u1s).
// Signs are compile-time per o -> folded into FFMA modifiers, 4 coeff regs.
template<int CBX>
__device__ __forceinline__ void sGateX(float* vr, float* vi, const float* __restrict__ u, int p) {
  const float u0  = u[0];
  const float u1s = p ? -u[1] : u[1];
  const float u2s = p ? -u[2] : u[2];
  const float u3  = u[3];
#pragma unroll
  for (int o = 0; o < 16; ++o) {
    const float qr = __shfl_xor_sync(0xffffffffu, vr[o], 16);
    const float qi = __shfl_xor_sync(0xffffffffu, vi[o], 16);
    const float ar = vr[o], ai = vi[o];
    if (((__popc(o) & 1) ^ CBX) == 0) {
      vr[o] = u0*ar - u1s*ai + u2s*qr - u3*qi;
      vi[o] = u0*ai + u1s*ar + u2s*qi + u3*qr;
    } else {
      vr[o] = -u2s*ar - u3*ai + u0*qr + u1s*qi;
      vi[o] = -u2s*ai + u3*ar + u0*qi - u1s*qr;
    }
  }
}

__global__ void __launch_bounds__(NT, 1)
qc_kernel(const float* __restrict__ x, const float* __restrict__ prx,
          const float* __restrict__ pry, const float* __restrict__ prz,
          const float* __restrict__ pent, float* __restrict__ out) {
  extern __shared__ float sm[];
  float2* st = reinterpret_cast<float2*>(sm);
  float2* vv = reinterpret_cast<float2*>(sm + OFF_V);
  const int tid  = threadIdx.x;
  const int lane = tid & 31;
  const int g    = (tid >> 5) * 16 + (lane & 15);   // window id 0..511
  const int p    = (lane >> 4) & 1;                 // window bit 4
  const int b    = blockIdx.x;

  // ---- prologue: gates for layers 1..3 (U' = Rz*Ry*Rx * RZ_ent[l-1]) ----
  if (tid < NGL * NQ) {
    const int q = tid % NQ;
    const int idx = tid + NQ;
    float cx, sx, cy, sy, cz, sz;
    sincosf(0.5f * prx[idx], &sx, &cx);
    sincosf(0.5f * pry[idx], &sy, &cy);
    sincosf(0.5f * prz[idx], &sz, &cz);
    const float r00x =  cy*cx, r00y =  sy*sx;
    const float r01x = -sy*cx, r01y = -cy*sx;
    const float r10x =  sy*cx, r10y = -cy*sx;
    const float r11x =  cy*cx, r11y = -sy*sx;
    float u0 = r00x*cz + r00y*sz, u1 = r00y*cz - r00x*sz;
    float u2 = r01x*cz + r01y*sz, u3 = r01y*cz - r01x*sz;
    float u4 = r10x*cz - r10y*sz, u5 = r10x*sz + r10y*cz;
    float u6 = r11x*cz - r11y*sz, u7 = r11x*sz + r11y*cz;
    if (q >= 1) {
      float c, s; sincosf(0.5f * pent[(tid / NQ) * NC + (q - 1)], &s, &c);
      float a;
      a = u0*c + u1*s;  u1 = u1*c - u0*s;  u0 = a;   // col 0 *= e^{-i t/2}
      a = u4*c + u5*s;  u5 = u5*c - u4*s;  u4 = a;
      a = u2*c - u3*s;  u3 = u3*c + u2*s;  u2 = a;   // col 1 *= e^{+i t/2}
      a = u6*c - u7*s;  u7 = u7*c + u6*s;  u6 = a;
    }
    float* u = sm + OFF_U + tid * 8;
    u[0] = u0; u[1] = u1; u[2] = u2; u[3] = u3;
    u[4] = u4; u[5] = u5; u[6] = u6; u[7] = u7;
  }
  // ---- layer-0 gates folded into product vectors: v_j = U_0(j)*(c_j,s_j)^T ----
  if (tid >= 64 && tid < 64 + NQ) {
    const int j = tid - 64;
    float cx, sx, cy, sy, cz, sz;
    sincosf(0.5f * prx[j], &sx, &cx);
    sincosf(0.5f * pry[j], &sy, &cy);
    sincosf(0.5f * prz[j], &sz, &cz);
    const float r00x =  cy*cx, r00y =  sy*sx;
    const float r01x = -sy*cx, r01y = -cy*sx;
    const float r10x =  sy*cx, r10y = -cy*sx;
    const float r11x =  cy*cx, r11y = -sy*sx;
    const float u0 = r00x*cz + r00y*sz, u1 = r00y*cz - r00x*sz;
    const float u2 = r01x*cz + r01y*sz, u3 = r01y*cz - r01x*sz;
    const float u4 = r10x*cz - r10y*sz, u5 = r10x*sz + r10y*cz;
    const float u6 = r11x*cz - r11y*sz, u7 = r11x*sz + r11y*cz;
    const float th = 0.5f * 3.14159265358979323846f * tanhf(x[b * NQ + j]);
    float c, s; sincosf(th, &s, &c);
    vv[j * 2 + 0] = make_float2(u0 * c + u2 * s, u1 * c + u3 * s);
    vv[j * 2 + 1] = make_float2(u4 * c + u6 * s, u5 * c + u7 * s);
  }
  __syncthreads();

  const float* ul1 = sm + OFF_U;
  const float* ul2 = sm + OFF_U + 14 * 8;
  const float* ul3 = sm + OFF_U + 28 * 8;
  const int cb = (g >> 4) & 1;          // qubit-4 value for S=5 windows (warp-uniform)
  float vr[16], vi[16];

  // ================= P1: synth + G1(0-4) + C1(0-3)  [S=0] =================
  {
    // amp(y) = prod v_j[x_j], x_j = y_j^y_{j-1}; y bits: 0-3=o, 4=p, 5-13=g
    float2 Pg = vv[5 * 2 + ((g ^ p) & 1)];
#pragma unroll
    for (int j = 6; j < NQ; ++j)
      Pg = cmul(Pg, vv[j * 2 + (((g >> (j - 5)) ^ (g >> (j - 6))) & 1)]);
    float2 t4[2];                      // o3 -> v4[p^o3]*Pg
    t4[0] = cmul(vv[4 * 2 + p], Pg);
    t4[1] = cmul(vv[4 * 2 + (p ^ 1)], Pg);
    float2 r34[4];                     // [o2 + 2*o3]
#pragma unroll
    for (int o2 = 0; o2 < 2; ++o2)
#pragma unroll
      for (int o3 = 0; o3 < 2; ++o3)
        r34[o2 + 2 * o3] = cmul(vv[3 * 2 + (o3 ^ o2)], t4[o3]);
    float2 qv[8];                      // [o1 + 2*o2 + 4*o3]
#pragma unroll
    for (int o1 = 0; o1 < 2; ++o1)
#pragma unroll
      for (int o2 = 0; o2 < 2; ++o2)
#pragma unroll
        for (int o3 = 0; o3 < 2; ++o3)
          qv[o1 + 2 * o2 + 4 * o3] = cmul(vv[2 * 2 + (o2 ^ o1)], r34[o2 + 2 * o3]);
    float2 e01[4];                     // [o0 + 2*o1]
#pragma unroll
    for (int o0 = 0; o0 < 2; ++o0)
#pragma unroll
      for (int o1 = 0; o1 < 2; ++o1)
        e01[o0 + 2 * o1] = cmul(vv[0 * 2 + o0], vv[1 * 2 + (o1 ^ o0)]);
#pragma unroll
    for (int o = 0; o < 16; ++o) {
      const float2 a = cmul(e01[o & 3], qv[(o >> 1) & 7]);
      vr[o] = a.x; vi[o] = a.y;
    }
    gateBit<0>(vr, vi, ul1 + 0 * 8);
    gateBit<1>(vr, vi, ul1 + 1 * 8);
    gateBit<2>(vr, vi, ul1 + 2 * 8);
    gateBit<3>(vr, vi, ul1 + 3 * 8);
    sGateX<0>(vr, vi, ul1 + 4 * 8, p);              // G1(4) + c3 merged
    store16<0, true>(st, g, p, vr, vi, 0);          // c0-c2 folded via PX relabel
  }
  __syncthreads();

  // ================= P2: G1(5-9) + C1(4-8)  [S=5] =================
  {
    load16<5>(st, g, p, vr, vi);
    gateBit<0>(vr, vi, ul1 + 5 * 8);
    gateBit<1>(vr, vi, ul1 + 6 * 8);
    gateBit<2>(vr, vi, ul1 + 7 * 8);
    gateBit<3>(vr, vi, ul1 + 8 * 8);
    if (cb) sGateX<1>(vr, vi, ul1 + 9 * 8, p);      // G1(9) + c8 merged (swap at par^cb)
    else    sGateX<0>(vr, vi, ul1 + 9 * 8, p);
    store16<5, true>(st, g, p, vr, vi, cb ? 15 : 0); // c4 (ctrl outside) + c5-c7 folded
  }
  __syncthreads();

  // ================= P3: G1(10-13) + C1(9-12) + G2(9-13)  [S=9] =================
  {
    load16<9>(st, g, p, vr, vi);
    gateBit<1>(vr, vi, ul1 + 10 * 8);
    gateBit<2>(vr, vi, ul1 + 11 * 8);
    gateBit<3>(vr, vi, ul1 + 12 * 8);
    sGateX<0>(vr, vi, ul1 + 13 * 8, p);              // G1(13) + c12 merged
    float wr[16], wi[16];                            // relabel c9-c11
#pragma unroll
    for (int o = 0; o < 16; ++o) { wr[pxm(o)] = vr[o]; wi[pxm(o)] = vi[o]; }
    gateBit<0>(wr, wi, ul2 + 9 * 8);
    gateBit<1>(wr, wi, ul2 + 10 * 8);
    gateBit<2>(wr, wi, ul2 + 11 * 8);
    gateBit<3>(wr, wi, ul2 + 12 * 8);
    sGate(wr, wi, ul2 + 13 * 8, p);
    store16<9, false>(st, g, p, wr, wi, 0);
  }
  __syncthreads();

  // ================= P4: G2(0-4) + C2(0-3)  [S=0] =================
  {
    load16<0>(st, g, p, vr, vi);
    gateBit<0>(vr, vi, ul2 + 0 * 8);
    gateBit<1>(vr, vi, ul2 + 1 * 8);
    gateBit<2>(vr, vi, ul2 + 2 * 8);
    gateBit<3>(vr, vi, ul2 + 3 * 8);
    sGateX<0>(vr, vi, ul2 + 4 * 8, p);
    store16<0, true>(st, g, p, vr, vi, 0);
  }
  __syncthreads();

  // ================= P5: G2(5-8) + C2(4-8)  [S=5] =================
  {
    load16<5>(st, g, p, vr, vi);
    gateBit<0>(vr, vi, ul2 + 5 * 8);
    gateBit<1>(vr, vi, ul2 + 6 * 8);
    gateBit<2>(vr, vi, ul2 + 7 * 8);
    gateBit<3>(vr, vi, ul2 + 8 * 8);
    // G2(9) already applied in P3; c8 exch folded into the store lane bit
    storeSwap16<5>(st, g, p, vr, vi, cb ? 15 : 0, cb);
  }
  __syncthreads();

  // ================= P6: C2(9-12) + G3(9-13)  [S=9] =================
  {
    loadSwap16<9>(st, g, p, vr, vi);                 // c12 folded into load lane bit
    float wr[16], wi[16];
#pragma unroll
    for (int o = 0; o < 16; ++o) { wr[pxm(o)] = vr[o]; wi[pxm(o)] = vi[o]; }
    gateBit<0>(wr, wi, ul3 + 9 * 8);
    gateBit<1>(wr, wi, ul3 + 10 * 8);
    gateBit<2>(wr, wi, ul3 + 11 * 8);
    gateBit<3>(wr, wi, ul3 + 12 * 8);
    sGate(wr, wi, ul3 + 13 * 8, p);
    store16<9, false>(st, g, p, wr, wi, 0);
  }
  __syncthreads();

  // ================= P7: G3(0-4) + C3(0-3)  [S=0] =================
  {
    load16<0>(st, g, p, vr, vi);
    gateBit<0>(vr, vi, ul3 + 0 * 8);
    gateBit<1>(vr, vi, ul3 + 1 * 8);
    gateBit<2>(vr, vi, ul3 + 2 * 8);
    gateBit<3>(vr, vi, ul3 + 3 * 8);
    sGateX<0>(vr, vi, ul3 + 4 * 8, p);
    store16<0, true>(st, g, p, vr, vi, 0);
  }
  __syncthreads();

  // ================= P8: G3(5-8) + C3(4-8)  [S=5] =================
  {
    load16<5>(st, g, p, vr, vi);
    gateBit<0>(vr, vi, ul3 + 5 * 8);
    gateBit<1>(vr, vi, ul3 + 6 * 8);
    gateBit<2>(vr, vi, ul3 + 7 * 8);
    gateBit<3>(vr, vi, ul3 + 8 * 8);
    storeSwap16<5>(st, g, p, vr, vi, cb ? 15 : 0, cb);
  }
  __syncthreads();

  // ================= P9: C3(9-12) + MEAS  [S=9] =================
  float acc[NQ];
  {
    load16<9>(st, g, p, vr, vi);
    float tot = 0.0f, s0 = 0.0f, s1 = 0.0f, s2 = 0.0f, s3 = 0.0f;
#pragma unroll
    for (int o = 0; o < 16; ++o) {
      const float pr = vr[o] * vr[o] + vi[o] * vi[o];
      const int m = pxm(o);              // labels after c9-c11 (no data movement)
      tot += pr;
      if (m & 1) s0 += pr;
      if (m & 2) s1 += pr;
      if (m & 4) s2 += pr;
      if (m & 8) s3 += pr;
    }
    acc[9]  = tot - 2.0f * s0;
    acc[10] = tot - 2.0f * s1;
    acc[11] = tot - 2.0f * s2;
    acc[12] = tot - 2.0f * s3;
    acc[13] = p ? (2.0f * s3 - tot) : (tot - 2.0f * s3);   // q13 = p ^ m3 (c12 folded)
#pragma unroll
    for (int q = 0; q < 9; ++q)
      acc[q] = ((g >> q) & 1) ? -tot : tot;
  }

  // ---- reduction ----
#pragma unroll
  for (int q = 0; q < NQ; ++q)
#pragma unroll
    for (int off = 16; off > 0; off >>= 1)
      acc[q] += __shfl_xor_sync(0xffffffffu, acc[q], off);
  const int warp = tid >> 5;
  __syncthreads();
  if ((tid & 31) == 0) {
#pragma unroll
    for (int q = 0; q < NQ; ++q) sm[OFF_RED + warp * NQ + q] = acc[q];
  }
  __syncthreads();
  if (tid < NQ) {
    float s = 0.0f;
#pragma unroll
    for (int w = 0; w < NWARP; ++w) s += sm[OFF_RED + w * NQ + tid];
    out[b * NQ + tid] = s;
  }
}

} // namespace qc

extern "C" void kernel_launch(void* const* d_in, const int* in_sizes, int n_in,
                              void* d_out, int out_size) {
  const float* x    = (const float*)d_in[0];
  const float* prx  = (const float*)d_in[1];
  const float* pry  = (const float*)d_in[2];
  const float* prz  = (const float*)d_in[3];
  const float* pent = (const float*)d_in[4];
  float* out = (float*)d_out;
  const int batch = in_sizes[0] / qc::NQ;   // 128
  cudaFuncSetAttribute(qc::qc_kernel, cudaFuncAttributeMaxDynamicSharedMemorySize,
                       qc::SMEM_BYTES);
  qc::qc_kernel<<<batch, qc::NT, qc::SMEM_BYTES>>>(x, prx, pry, prz, pent, out);
}